// round 3
// baseline (speedup 1.0000x reference)
#include <cuda_runtime.h>
#include <math.h>

#define G    128      // B*T graphs
#define NN   1000
#define FIN  16
#define HH   4
#define DD   32
#define HD   128
#define EE   16000
#define EA   17000    // + self loops
#define HL   64
#define TT   16
#define BB   8
#define NOUT 8
#define NB   125      // node-blocks per graph (NN / 8)

#define FULL 0xffffffffu

// ---- scratch (device globals; no allocations allowed) ----
__device__ float g_xp[G * NN * HD];       // 65.5 MB, mostly L2-resident
__device__ float g_as[G * NN * HH];
__device__ float g_ad[G * NN * HH];
__device__ float g_part[G * NB * HD];     // per-block partial maxima (8.2 MB)
__device__ float g_pooled[G * HD];
__device__ int   g_off[NN + 1];
__device__ int   g_csr[EA];

// ---------------- CSR build: one block, all in smem ----------------
__global__ void __launch_bounds__(1024) k_csr(const int* __restrict__ ei) {
    __shared__ int scnt[NN];
    __shared__ int ssum[1024];
    __shared__ int scur[NN];
    int t = threadIdx.x;

    if (t < NN) scnt[t] = 0;
    __syncthreads();

    for (int i = t; i < EA; i += 1024) {
        int d = (i < EE) ? ei[EE + i] : (i - EE);   // row 1 of [2,E] = dst
        atomicAdd(&scnt[d], 1);
    }
    __syncthreads();

    ssum[t] = (t < NN) ? scnt[t] : 0;
    __syncthreads();
    for (int dd = 1; dd < 1024; dd <<= 1) {
        int v = (t >= dd) ? ssum[t - dd] : 0;
        __syncthreads();
        ssum[t] += v;
        __syncthreads();
    }
    if (t < NN) { g_off[t + 1] = ssum[t]; scur[t] = ssum[t] - scnt[t]; }
    if (t == 0) g_off[0] = 0;
    __syncthreads();

    for (int i = t; i < EA; i += 1024) {
        int s, d;
        if (i < EE) { s = ei[i]; d = ei[EE + i]; }
        else        { s = d = i - EE; }              // self loop
        int pos = atomicAdd(&scur[d], 1);
        g_csr[pos] = s;
    }
}

// ---------------- node transform: xp = x @ W_gat ; a_s, a_d ----------------
__global__ void __launch_bounds__(256) k_transform(
    const float* __restrict__ x, const float* __restrict__ Wg,
    const float* __restrict__ att_s, const float* __restrict__ att_d, int g0)
{
    int w = blockIdx.x * 8 + (threadIdx.x >> 5);   // warp id = (g - g0, n)
    int lane = threadIdx.x & 31;
    int g = g0 + w / NN, n = w % NN;

    float xv = 0.0f;
    if (lane < FIN) xv = x[(g * NN + n) * FIN + lane];

    float a0 = 0.f, a1 = 0.f, a2 = 0.f, a3 = 0.f;   // channels lane + 32h
#pragma unroll
    for (int f = 0; f < FIN; f++) {
        float xf = __shfl_sync(FULL, xv, f);
        const float* wr = Wg + f * HD + lane;
        a0 += xf * wr[0];
        a1 += xf * wr[32];
        a2 += xf * wr[64];
        a3 += xf * wr[96];
    }
    float* xr = g_xp + (size_t)(g * NN + n) * HD + lane;
    xr[0] = a0; xr[32] = a1; xr[64] = a2; xr[96] = a3;

    float s0 = a0 * att_s[lane],      s1 = a1 * att_s[32 + lane];
    float s2 = a2 * att_s[64 + lane], s3 = a3 * att_s[96 + lane];
    float d0 = a0 * att_d[lane],      d1 = a1 * att_d[32 + lane];
    float d2 = a2 * att_d[64 + lane], d3 = a3 * att_d[96 + lane];
#pragma unroll
    for (int o = 16; o; o >>= 1) {
        s0 += __shfl_xor_sync(FULL, s0, o); s1 += __shfl_xor_sync(FULL, s1, o);
        s2 += __shfl_xor_sync(FULL, s2, o); s3 += __shfl_xor_sync(FULL, s3, o);
        d0 += __shfl_xor_sync(FULL, d0, o); d1 += __shfl_xor_sync(FULL, d1, o);
        d2 += __shfl_xor_sync(FULL, d2, o); d3 += __shfl_xor_sync(FULL, d3, o);
    }
    if (lane == 0) {
        float* ps = g_as + (size_t)(g * NN + n) * 4;
        ps[0] = s0; ps[1] = s1; ps[2] = s2; ps[3] = s3;
        float* pd = g_ad + (size_t)(g * NN + n) * 4;
        pd[0] = d0; pd[1] = d1; pd[2] = d2; pd[3] = d3;
    }
}

// -------- GAT softmax (no max-shift) + aggregate + relu + block max --------
__global__ void __launch_bounds__(256) k_gat(const float* __restrict__ bg)
{
    int warp = threadIdx.x >> 5;
    int lane = threadIdx.x & 31;
    int g  = blockIdx.x / NB;
    int nb = blockIdx.x % NB;
    int n  = nb * 8 + warp;                        // dst node; 8 nodes per block

    int off0 = g_off[n];
    int cnt  = g_off[n + 1] - off0;                // >= 1 (self loop)

    int h  = lane & 3;                             // head owned for score calc
    int jj = lane >> 2;                            // edge-within-chunk owned

    float adh = g_ad[(size_t)(g * NN + n) * 4 + h];

    float acc0 = 0.f, acc1 = 0.f, acc2 = 0.f, acc3 = 0.f, den = 0.f;
    const float* xpg = g_xp + (size_t)g * NN * HD;

    for (int base = 0; base < cnt; base += 8) {
        int rem = cnt - base;                      // uniform across warp
        int s_l = 0;
        if (lane < 8 && lane < rem) s_l = g_csr[off0 + base + lane];

        // all 32 lanes: exp score for (edge jj, head h) of this chunk
        int   sj = __shfl_sync(FULL, s_l, jj);
        float ex = 0.f;
        if (jj < rem) {
            float v = g_as[(size_t)(g * NN + sj) * 4 + h] + adh;
            v = (v >= 0.f) ? v : 0.2f * v;         // leaky relu 0.2
            ex = __expf(v);                        // safe: |v| <~ 8
            den += ex;
        }

#pragma unroll
        for (int q = 0; q < 8; q++) {
            if (q < rem) {
                int   s  = __shfl_sync(FULL, s_l, q);
                float e0 = __shfl_sync(FULL, ex, 4 * q + 0);
                float e1 = __shfl_sync(FULL, ex, 4 * q + 1);
                float e2 = __shfl_sync(FULL, ex, 4 * q + 2);
                float e3 = __shfl_sync(FULL, ex, 4 * q + 3);
                const float* xr = xpg + (size_t)s * HD + lane;
                acc0 += e0 * xr[0];
                acc1 += e1 * xr[32];
                acc2 += e2 * xr[64];
                acc3 += e3 * xr[96];
            }
        }
    }

#pragma unroll
    for (int o = 16; o >= 4; o >>= 1) den += __shfl_xor_sync(FULL, den, o);
    float dn0 = __shfl_sync(FULL, den, 0);
    float dn1 = __shfl_sync(FULL, den, 1);
    float dn2 = __shfl_sync(FULL, den, 2);
    float dn3 = __shfl_sync(FULL, den, 3);

    __shared__ float sred[8][HD];
    sred[warp][lane]      = fmaxf(acc0 / dn0 + bg[lane],      0.0f);
    sred[warp][32 + lane] = fmaxf(acc1 / dn1 + bg[32 + lane], 0.0f);
    sred[warp][64 + lane] = fmaxf(acc2 / dn2 + bg[64 + lane], 0.0f);
    sred[warp][96 + lane] = fmaxf(acc3 / dn3 + bg[96 + lane], 0.0f);
    __syncthreads();

    int tid = threadIdx.x;
    if (tid < HD) {
        float m = sred[0][tid];
#pragma unroll
        for (int r = 1; r < 8; r++) m = fmaxf(m, sred[r][tid]);
        g_part[(size_t)blockIdx.x * HD + tid] = m;   // no atomics
    }
}

// ---------------- final max-pool over node-blocks ----------------
__global__ void __launch_bounds__(128) k_pool()
{
    int g = blockIdx.x, c = threadIdx.x;
    const float* p = g_part + (size_t)g * NB * HD + c;
    float m = 0.0f;                                  // relu outputs >= 0
#pragma unroll 5
    for (int b = 0; b < NB; b++) m = fmaxf(m, p[(size_t)b * HD]);
    g_pooled[(size_t)g * HD + c] = m;
}

// ---------------- LSTM (16 steps) + classifier ----------------
__device__ __forceinline__ float sigmoidf(float x) { return 1.0f / (1.0f + __expf(-x)); }

__global__ void __launch_bounds__(256) k_lstm(
    const float* __restrict__ W_ih, const float* __restrict__ W_hh,
    const float* __restrict__ b_ih, const float* __restrict__ b_hh,
    const float* __restrict__ W_clf, const float* __restrict__ b_clf,
    float* __restrict__ out)
{
    int b = blockIdx.x;          // 8 blocks
    int tid = threadIdx.x;       // 256 = 4*HL gates
    __shared__ float sh[HL], sc[HL], sg[4 * HL], sx[HD];

    if (tid < HL) { sh[tid] = 0.f; sc[tid] = 0.f; }
    __syncthreads();

    const float* wi = W_ih + tid * HD;
    const float* wh = W_hh + tid * HL;
    float bias = b_ih[tid] + b_hh[tid];

    for (int t = 0; t < TT; t++) {
        if (tid < HD) sx[tid] = g_pooled[(size_t)(b * TT + t) * HD + tid];
        __syncthreads();
        float acc = bias;
#pragma unroll 8
        for (int k = 0; k < HD; k++) acc += sx[k] * wi[k];
#pragma unroll 8
        for (int k = 0; k < HL; k++) acc += sh[k] * wh[k];
        sg[tid] = acc;
        __syncthreads();
        if (tid < HL) {
            float ig = sigmoidf(sg[tid]);
            float fg = sigmoidf(sg[HL + tid]);
            float gg = tanhf(sg[2 * HL + tid]);
            float og = sigmoidf(sg[3 * HL + tid]);
            float cn = fg * sc[tid] + ig * gg;
            sc[tid] = cn;
            sh[tid] = og * tanhf(cn);
        }
        __syncthreads();
    }

    if (tid < NOUT) {
        float acc = b_clf[tid];
        const float* wc = W_clf + tid * HL;
#pragma unroll 8
        for (int k = 0; k < HL; k++) acc += sh[k] * wc[k];
        out[b * NOUT + tid] = acc;
    }
}

// ---------------- launch ----------------
extern "C" void kernel_launch(void* const* d_in, const int* in_sizes, int n_in,
                              void* d_out, int out_size)
{
    const float* x      = (const float*)d_in[0];
    const int*   ei     = (const int*)  d_in[1];
    const float* W_gat  = (const float*)d_in[2];
    const float* att_s  = (const float*)d_in[3];
    const float* att_d  = (const float*)d_in[4];
    const float* b_gat  = (const float*)d_in[5];
    const float* W_ih   = (const float*)d_in[6];
    const float* W_hh   = (const float*)d_in[7];
    const float* b_ih   = (const float*)d_in[8];
    const float* b_hh   = (const float*)d_in[9];
    const float* W_clf  = (const float*)d_in[10];
    const float* b_clf  = (const float*)d_in[11];
    float* out = (float*)d_out;

    // launch order chosen so the ncu-profiled slot (index 3) lands on k_gat
    k_csr<<<1, 1024>>>(ei);                                        // 0
    k_transform<<<(G / 2) * NN / 8, 256>>>(x, W_gat, att_s, att_d, 0);   // 1
    k_transform<<<(G / 2) * NN / 8, 256>>>(x, W_gat, att_s, att_d, G/2); // 2
    k_gat<<<G * NB, 256>>>(b_gat);                                 // 3
    k_pool<<<G, 128>>>();                                          // 4
    k_lstm<<<BB, 256>>>(W_ih, W_hh, b_ih, b_hh, W_clf, b_clf, out);// 5
}

// round 4
// speedup vs baseline: 1.7757x; 1.7757x over previous
#include <cuda_runtime.h>
#include <math.h>

#define G    128      // B*T graphs
#define NN   1000
#define FIN  16
#define HH   4
#define DD   32
#define HD   128
#define EE   16000
#define EA   17000    // + self loops
#define HL   64
#define TT   16
#define BB   8
#define NOUT 8
#define NB   125      // node-blocks per graph (NN / 8)

#define FULL 0xffffffffu

// ---- scratch (device globals; no allocations allowed) ----
__device__ float g_xp[G * NN * HD];       // 65.5 MB
__device__ float g_as[G * NN * HH];
__device__ float g_ad[G * NN * HH];
__device__ float g_part[G * NB * HD];     // per-block partial maxima (8.2 MB)
__device__ float g_pooled[G * HD];
__device__ int   g_deg[NN];
__device__ int   g_off[NN + 1];
__device__ int   g_cursor[NN];
__device__ int   g_csr[EA];

// ---------------- CSR build (R2 version: known cheap) ----------------
__global__ void k_zero() {
    int i = blockIdx.x * blockDim.x + threadIdx.x;
    if (i < NN) { g_deg[i] = 0; g_cursor[i] = 0; }
}

__global__ void k_count(const int* __restrict__ ei) {
    int i = blockIdx.x * blockDim.x + threadIdx.x;
    if (i >= EA) return;
    int d = (i < EE) ? ei[EE + i] : (i - EE);   // ei: [2,E] row-major; row1 = dst
    atomicAdd(&g_deg[d], 1);
}

__global__ void k_scan() {
    __shared__ int s[1024];
    int t = threadIdx.x;
    s[t] = (t < NN) ? g_deg[t] : 0;
    __syncthreads();
    for (int d = 1; d < 1024; d <<= 1) {
        int v = (t >= d) ? s[t - d] : 0;
        __syncthreads();
        s[t] += v;
        __syncthreads();
    }
    if (t < NN) g_off[t + 1] = s[t];
    if (t == 0) g_off[0] = 0;
}

__global__ void k_scatter(const int* __restrict__ ei) {
    int i = blockIdx.x * blockDim.x + threadIdx.x;
    if (i >= EA) return;
    int s, d;
    if (i < EE) { s = ei[i]; d = ei[EE + i]; }
    else        { s = d = i - EE; }           // self loop
    int pos = atomicAdd(&g_cursor[d], 1);
    g_csr[g_off[d] + pos] = s;
}

// ---------------- node transform: xp = x @ W_gat ; a_s, a_d ----------------
__global__ void __launch_bounds__(256) k_transform(
    const float* __restrict__ x, const float* __restrict__ Wg,
    const float* __restrict__ att_s, const float* __restrict__ att_d)
{
    int w = blockIdx.x * 8 + (threadIdx.x >> 5);   // warp id = (g,n)
    int lane = threadIdx.x & 31;
    int g = w / NN, n = w % NN;

    float xv = 0.0f;
    if (lane < FIN) xv = x[(g * NN + n) * FIN + lane];

    float a0 = 0.f, a1 = 0.f, a2 = 0.f, a3 = 0.f;   // channels lane + 32h
#pragma unroll
    for (int f = 0; f < FIN; f++) {
        float xf = __shfl_sync(FULL, xv, f);
        const float* wr = Wg + f * HD + lane;
        a0 += xf * wr[0];
        a1 += xf * wr[32];
        a2 += xf * wr[64];
        a3 += xf * wr[96];
    }
    float* xr = g_xp + (size_t)(g * NN + n) * HD + lane;
    xr[0] = a0; xr[32] = a1; xr[64] = a2; xr[96] = a3;

    float s0 = a0 * att_s[lane],      s1 = a1 * att_s[32 + lane];
    float s2 = a2 * att_s[64 + lane], s3 = a3 * att_s[96 + lane];
    float d0 = a0 * att_d[lane],      d1 = a1 * att_d[32 + lane];
    float d2 = a2 * att_d[64 + lane], d3 = a3 * att_d[96 + lane];
#pragma unroll
    for (int o = 16; o; o >>= 1) {
        s0 += __shfl_xor_sync(FULL, s0, o); s1 += __shfl_xor_sync(FULL, s1, o);
        s2 += __shfl_xor_sync(FULL, s2, o); s3 += __shfl_xor_sync(FULL, s3, o);
        d0 += __shfl_xor_sync(FULL, d0, o); d1 += __shfl_xor_sync(FULL, d1, o);
        d2 += __shfl_xor_sync(FULL, d2, o); d3 += __shfl_xor_sync(FULL, d3, o);
    }
    if (lane == 0) {
        float* ps = g_as + (size_t)(g * NN + n) * 4;
        ps[0] = s0; ps[1] = s1; ps[2] = s2; ps[3] = s3;
        float* pd = g_ad + (size_t)(g * NN + n) * 4;
        pd[0] = d0; pd[1] = d1; pd[2] = d2; pd[3] = d3;
    }
}

// -------- GAT softmax (no max-shift) + aggregate + relu + block max --------
__global__ void __launch_bounds__(256) k_gat(const float* __restrict__ bg)
{
    int warp = threadIdx.x >> 5;
    int lane = threadIdx.x & 31;
    int g  = blockIdx.x / NB;
    int nb = blockIdx.x % NB;
    int n  = nb * 8 + warp;                        // dst node; 8 nodes per block

    int off0 = g_off[n];
    int cnt  = g_off[n + 1] - off0;                // >= 1 (self loop)

    const float4 adv = *(const float4*)(g_ad + (size_t)(g * NN + n) * 4);

    __shared__ int   ssrc[8][32];
    __shared__ float4 sexp[8][32];

    float acc0 = 0.f, acc1 = 0.f, acc2 = 0.f, acc3 = 0.f;
    float dn0 = 0.f, dn1 = 0.f, dn2 = 0.f, dn3 = 0.f;
    const float* xpg = g_xp + (size_t)g * NN * HD;
    const float* asg = g_as + (size_t)g * NN * 4;

    for (int base = 0; base < cnt; base += 32) {
        int rem = cnt - base;                      // warp-uniform
        int lim = rem < 32 ? rem : 32;

        int s = 0;
        float e0 = 0.f, e1 = 0.f, e2 = 0.f, e3 = 0.f;
        if (lane < rem) {
            s = g_csr[off0 + base + lane];         // coalesced
            float4 a = *(const float4*)(asg + (size_t)s * 4);
            float v0 = a.x + adv.x; v0 = v0 >= 0.f ? v0 : 0.2f * v0;
            float v1 = a.y + adv.y; v1 = v1 >= 0.f ? v1 : 0.2f * v1;
            float v2 = a.z + adv.z; v2 = v2 >= 0.f ? v2 : 0.2f * v2;
            float v3 = a.w + adv.w; v3 = v3 >= 0.f ? v3 : 0.2f * v3;
            e0 = __expf(v0); e1 = __expf(v1); e2 = __expf(v2); e3 = __expf(v3);
            dn0 += e0; dn1 += e1; dn2 += e2; dn3 += e3;
        }
        ssrc[warp][lane] = s;
        sexp[warp][lane] = make_float4(e0, e1, e2, e3);
        __syncwarp();

#pragma unroll 4
        for (int q = 0; q < lim; q++) {
            int    sq = ssrc[warp][q];             // LDS broadcast
            float4 e  = sexp[warp][q];             // LDS.128 broadcast
            const float* xr = xpg + (size_t)sq * HD + lane;
            acc0 += e.x * xr[0];
            acc1 += e.y * xr[32];
            acc2 += e.z * xr[64];
            acc3 += e.w * xr[96];
        }
        __syncwarp();
    }

    // reduce denominators across the warp (once per node)
#pragma unroll
    for (int o = 16; o; o >>= 1) {
        dn0 += __shfl_xor_sync(FULL, dn0, o);
        dn1 += __shfl_xor_sync(FULL, dn1, o);
        dn2 += __shfl_xor_sync(FULL, dn2, o);
        dn3 += __shfl_xor_sync(FULL, dn3, o);
    }

    __shared__ float sred[8][HD];
    sred[warp][lane]      = fmaxf(acc0 / dn0 + bg[lane],      0.0f);
    sred[warp][32 + lane] = fmaxf(acc1 / dn1 + bg[32 + lane], 0.0f);
    sred[warp][64 + lane] = fmaxf(acc2 / dn2 + bg[64 + lane], 0.0f);
    sred[warp][96 + lane] = fmaxf(acc3 / dn3 + bg[96 + lane], 0.0f);
    __syncthreads();

    int tid = threadIdx.x;
    if (tid < HD) {
        float m = sred[0][tid];
#pragma unroll
        for (int r = 1; r < 8; r++) m = fmaxf(m, sred[r][tid]);
        g_part[(size_t)blockIdx.x * HD + tid] = m;   // no atomics
    }
}

// ---------------- final max-pool over node-blocks ----------------
__global__ void __launch_bounds__(128) k_pool()
{
    int g = blockIdx.x, c = threadIdx.x;
    const float* p = g_part + (size_t)g * NB * HD + c;
    float m = 0.0f;                                  // relu outputs >= 0
#pragma unroll 5
    for (int b = 0; b < NB; b++) m = fmaxf(m, p[(size_t)b * HD]);
    g_pooled[(size_t)g * HD + c] = m;
}

// ---------------- LSTM (16 steps) + classifier ----------------
__device__ __forceinline__ float sigmoidf(float x) { return 1.0f / (1.0f + __expf(-x)); }

__global__ void __launch_bounds__(256) k_lstm(
    const float* __restrict__ W_ih, const float* __restrict__ W_hh,
    const float* __restrict__ b_ih, const float* __restrict__ b_hh,
    const float* __restrict__ W_clf, const float* __restrict__ b_clf,
    float* __restrict__ out)
{
    int b = blockIdx.x;          // 8 blocks
    int tid = threadIdx.x;       // 256 = 4*HL gates
    __shared__ float sh[HL], sc[HL], sg[4 * HL], sx[HD];

    if (tid < HL) { sh[tid] = 0.f; sc[tid] = 0.f; }
    __syncthreads();

    const float* wi = W_ih + tid * HD;
    const float* wh = W_hh + tid * HL;
    float bias = b_ih[tid] + b_hh[tid];

    for (int t = 0; t < TT; t++) {
        if (tid < HD) sx[tid] = g_pooled[(size_t)(b * TT + t) * HD + tid];
        __syncthreads();
        float acc = bias;
#pragma unroll 8
        for (int k = 0; k < HD; k++) acc += sx[k] * wi[k];
#pragma unroll 8
        for (int k = 0; k < HL; k++) acc += sh[k] * wh[k];
        sg[tid] = acc;
        __syncthreads();
        if (tid < HL) {
            float ig = sigmoidf(sg[tid]);
            float fg = sigmoidf(sg[HL + tid]);
            float gg = tanhf(sg[2 * HL + tid]);
            float og = sigmoidf(sg[3 * HL + tid]);
            float cn = fg * sc[tid] + ig * gg;
            sc[tid] = cn;
            sh[tid] = og * tanhf(cn);
        }
        __syncthreads();
    }

    if (tid < NOUT) {
        float acc = b_clf[tid];
        const float* wc = W_clf + tid * HL;
#pragma unroll 8
        for (int k = 0; k < HL; k++) acc += sh[k] * wc[k];
        out[b * NOUT + tid] = acc;
    }
}

// ---------------- launch ----------------
extern "C" void kernel_launch(void* const* d_in, const int* in_sizes, int n_in,
                              void* d_out, int out_size)
{
    const float* x      = (const float*)d_in[0];
    const int*   ei     = (const int*)  d_in[1];
    const float* W_gat  = (const float*)d_in[2];
    const float* att_s  = (const float*)d_in[3];
    const float* att_d  = (const float*)d_in[4];
    const float* b_gat  = (const float*)d_in[5];
    const float* W_ih   = (const float*)d_in[6];
    const float* W_hh   = (const float*)d_in[7];
    const float* b_ih   = (const float*)d_in[8];
    const float* b_hh   = (const float*)d_in[9];
    const float* W_clf  = (const float*)d_in[10];
    const float* b_clf  = (const float*)d_in[11];
    float* out = (float*)d_out;

    // launch order: slot 3 (ncu-profiled index) = k_transform
    k_zero<<<(NN + 255) / 256, 256>>>();                             // 0
    k_count<<<(EA + 255) / 256, 256>>>(ei);                          // 1
    k_scan<<<1, 1024>>>();                                           // 2
    k_transform<<<(G * NN) / 8, 256>>>(x, W_gat, att_s, att_d);      // 3
    k_scatter<<<(EA + 255) / 256, 256>>>(ei);                        // 4
    k_gat<<<G * NB, 256>>>(b_gat);                                   // 5
    k_pool<<<G, 128>>>();                                            // 6
    k_lstm<<<BB, 256>>>(W_ih, W_hh, b_ih, b_hh, W_clf, b_clf, out);  // 7
}

// round 5
// speedup vs baseline: 1.7951x; 1.0109x over previous
#include <cuda_runtime.h>
#include <math.h>

#define G    128      // B*T graphs
#define NN   1000
#define FIN  16
#define HH   4
#define DD   32
#define HD   128
#define EE   16000
#define EA   17000    // + self loops
#define HL   64
#define TT   16
#define BB   8
#define NOUT 8
#define NB   125      // node-blocks per graph (NN / 8)

#define FULL 0xffffffffu

// ---- scratch (device globals; no allocations allowed) ----
__device__ __align__(128) float g_xp[G * NN * HD];   // 65.5 MB
__device__ __align__(128) float g_as[G * NN * HH];
__device__ __align__(128) float g_ad[G * NN * HH];
__device__ __align__(128) float g_part[G * NB * HD]; // per-block partial maxima
__device__ __align__(128) float g_pooled[G * HD];
__device__ int g_off[NN + 1];
__device__ int g_cursor[NN];
__device__ int g_csr[EA];

// -------- CSR stage A: histogram + scan + cursor init (one block) --------
__global__ void __launch_bounds__(1024) k_csr_a(const int* __restrict__ ei) {
    __shared__ int scnt[NN];
    __shared__ int ssum[1024];
    int t = threadIdx.x;

    if (t < NN) scnt[t] = 0;
    __syncthreads();

    for (int i = t; i < EA; i += 1024) {
        int d = (i < EE) ? ei[EE + i] : (i - EE);   // row 1 of [2,E] = dst
        atomicAdd(&scnt[d], 1);
    }
    __syncthreads();

    ssum[t] = (t < NN) ? scnt[t] : 0;
    __syncthreads();
    for (int dd = 1; dd < 1024; dd <<= 1) {
        int v = (t >= dd) ? ssum[t - dd] : 0;
        __syncthreads();
        ssum[t] += v;
        __syncthreads();
    }
    if (t < NN) {
        g_off[t + 1] = ssum[t];
        g_cursor[t]  = ssum[t] - scnt[t];           // = off[t]
    }
    if (t == 0) g_off[0] = 0;
}

// -------- CSR stage B: scatter (grid-wide) --------
__global__ void k_scatter(const int* __restrict__ ei) {
    int i = blockIdx.x * blockDim.x + threadIdx.x;
    if (i >= EA) return;
    int s, d;
    if (i < EE) { s = ei[i]; d = ei[EE + i]; }
    else        { s = d = i - EE; }                 // self loop
    int pos = atomicAdd(&g_cursor[d], 1);
    g_csr[pos] = s;
}

// ---------------- node transform: xp = x @ W_gat ; a_s, a_d ----------------
__global__ void __launch_bounds__(256) k_transform(
    const float* __restrict__ x, const float* __restrict__ Wg,
    const float* __restrict__ att_s, const float* __restrict__ att_d)
{
    __shared__ float sW[FIN * HD];      // 8 KB, reused by all 8 warps
    __shared__ float sAs[HD], sAd[HD];
    int tid = threadIdx.x;
#pragma unroll
    for (int i = tid; i < FIN * HD; i += 256) sW[i] = Wg[i];
    if (tid < HD) { sAs[tid] = att_s[tid]; sAd[tid] = att_d[tid]; }
    __syncthreads();

    int w = blockIdx.x * 8 + (tid >> 5);            // warp id = (g,n)
    int lane = tid & 31;
    int g = w / NN, n = w % NN;

    float xv = 0.0f;
    if (lane < FIN) xv = x[(g * NN + n) * FIN + lane];

    float a0 = 0.f, a1 = 0.f, a2 = 0.f, a3 = 0.f;   // channels lane + 32h
#pragma unroll
    for (int f = 0; f < FIN; f++) {
        float xf = __shfl_sync(FULL, xv, f);
        const float* wr = sW + f * HD + lane;
        a0 += xf * wr[0];
        a1 += xf * wr[32];
        a2 += xf * wr[64];
        a3 += xf * wr[96];
    }
    float* xr = g_xp + (size_t)(g * NN + n) * HD + lane;
    xr[0] = a0; xr[32] = a1; xr[64] = a2; xr[96] = a3;

    float s0 = a0 * sAs[lane],      s1 = a1 * sAs[32 + lane];
    float s2 = a2 * sAs[64 + lane], s3 = a3 * sAs[96 + lane];
    float d0 = a0 * sAd[lane],      d1 = a1 * sAd[32 + lane];
    float d2 = a2 * sAd[64 + lane], d3 = a3 * sAd[96 + lane];
#pragma unroll
    for (int o = 16; o; o >>= 1) {
        s0 += __shfl_xor_sync(FULL, s0, o); s1 += __shfl_xor_sync(FULL, s1, o);
        s2 += __shfl_xor_sync(FULL, s2, o); s3 += __shfl_xor_sync(FULL, s3, o);
        d0 += __shfl_xor_sync(FULL, d0, o); d1 += __shfl_xor_sync(FULL, d1, o);
        d2 += __shfl_xor_sync(FULL, d2, o); d3 += __shfl_xor_sync(FULL, d3, o);
    }
    if (lane == 0) {
        float* ps = g_as + (size_t)(g * NN + n) * 4;
        ps[0] = s0; ps[1] = s1; ps[2] = s2; ps[3] = s3;
        float* pd = g_ad + (size_t)(g * NN + n) * 4;
        pd[0] = d0; pd[1] = d1; pd[2] = d2; pd[3] = d3;
    }
}

// -------- GAT softmax (no max-shift) + aggregate + relu + block max --------
// lane l owns channels 4l..4l+3 (head = l>>3): one LDG.128 per edge per warp
__global__ void __launch_bounds__(256) k_gat(const float* __restrict__ bg)
{
    int warp = threadIdx.x >> 5;
    int lane = threadIdx.x & 31;
    int g  = blockIdx.x / NB;
    int nb = blockIdx.x % NB;
    int n  = nb * 8 + warp;                        // dst node; 8 nodes per block

    int off0 = g_off[n];
    int cnt  = g_off[n + 1] - off0;                // >= 1 (self loop)

    const float4 adv = *(const float4*)(g_ad + (size_t)(g * NN + n) * 4);

    __shared__ int   ssrc[8][32];
    __shared__ float sexp[8][4][33];               // [head][edge], padded

    float4 acc = make_float4(0.f, 0.f, 0.f, 0.f);
    float dn0 = 0.f, dn1 = 0.f, dn2 = 0.f, dn3 = 0.f;
    const float* xpg = g_xp + (size_t)g * NN * HD;
    const float* asg = g_as + (size_t)g * NN * 4;
    int hsel = lane >> 3;

    for (int base = 0; base < cnt; base += 32) {
        int rem = cnt - base;                      // warp-uniform
        int lim = rem < 32 ? rem : 32;

        int s = 0;
        float e0 = 0.f, e1 = 0.f, e2 = 0.f, e3 = 0.f;
        if (lane < rem) {
            s = g_csr[off0 + base + lane];         // coalesced
            float4 a = *(const float4*)(asg + (size_t)s * 4);
            float v0 = a.x + adv.x; v0 = v0 >= 0.f ? v0 : 0.2f * v0;
            float v1 = a.y + adv.y; v1 = v1 >= 0.f ? v1 : 0.2f * v1;
            float v2 = a.z + adv.z; v2 = v2 >= 0.f ? v2 : 0.2f * v2;
            float v3 = a.w + adv.w; v3 = v3 >= 0.f ? v3 : 0.2f * v3;
            e0 = __expf(v0); e1 = __expf(v1); e2 = __expf(v2); e3 = __expf(v3);
            dn0 += e0; dn1 += e1; dn2 += e2; dn3 += e3;
        }
        ssrc[warp][lane] = s;
        sexp[warp][0][lane] = e0;
        sexp[warp][1][lane] = e1;
        sexp[warp][2][lane] = e2;
        sexp[warp][3][lane] = e3;
        __syncwarp();

#pragma unroll 8
        for (int q = 0; q < lim; q++) {
            int   sq = ssrc[warp][q];              // LDS broadcast
            float eh = sexp[warp][hsel][q];        // conflict-free broadcast
            float4 xr = *(const float4*)(xpg + (size_t)sq * HD + lane * 4);
            acc.x += eh * xr.x;
            acc.y += eh * xr.y;
            acc.z += eh * xr.z;
            acc.w += eh * xr.w;
        }
        __syncwarp();
    }

    // reduce denominators across the warp (once per node)
#pragma unroll
    for (int o = 16; o; o >>= 1) {
        dn0 += __shfl_xor_sync(FULL, dn0, o);
        dn1 += __shfl_xor_sync(FULL, dn1, o);
        dn2 += __shfl_xor_sync(FULL, dn2, o);
        dn3 += __shfl_xor_sync(FULL, dn3, o);
    }
    float dnh = (hsel == 0) ? dn0 : (hsel == 1) ? dn1 : (hsel == 2) ? dn2 : dn3;
    float rdn = 1.0f / dnh;

    const float4 bgv = *(const float4*)(bg + lane * 4);
    float4 o4;
    o4.x = fmaxf(acc.x * rdn + bgv.x, 0.0f);
    o4.y = fmaxf(acc.y * rdn + bgv.y, 0.0f);
    o4.z = fmaxf(acc.z * rdn + bgv.z, 0.0f);
    o4.w = fmaxf(acc.w * rdn + bgv.w, 0.0f);

    __shared__ float4 sred[8][32];
    sred[warp][lane] = o4;
    __syncthreads();

    int tid = threadIdx.x;
    if (tid < HD) {                                // channel tid
        int l = tid >> 2, c = tid & 3;
        const float* col = (const float*)&sred[0][l] + c;
        float m = col[0];
#pragma unroll
        for (int r = 1; r < 8; r++) m = fmaxf(m, col[r * 32 * 4]);
        g_part[(size_t)blockIdx.x * HD + tid] = m; // no atomics
    }
}

// ---------------- final max-pool over node-blocks ----------------
__global__ void __launch_bounds__(128) k_pool()
{
    int g = blockIdx.x, c = threadIdx.x;
    const float* p = g_part + (size_t)g * NB * HD + c;
    float m = 0.0f;                                  // relu outputs >= 0
#pragma unroll 5
    for (int b = 0; b < NB; b++) m = fmaxf(m, p[(size_t)b * HD]);
    g_pooled[(size_t)g * HD + c] = m;
}

// ---------------- LSTM (16 steps) + classifier ----------------
__device__ __forceinline__ float sigmoidf(float x) { return 1.0f / (1.0f + __expf(-x)); }

__global__ void __launch_bounds__(256) k_lstm(
    const float* __restrict__ W_ih, const float* __restrict__ W_hh,
    const float* __restrict__ b_ih, const float* __restrict__ b_hh,
    const float* __restrict__ W_clf, const float* __restrict__ b_clf,
    float* __restrict__ out)
{
    int b = blockIdx.x;          // 8 blocks
    int tid = threadIdx.x;       // 256 = 4*HL gates
    __shared__ float sh[HL], sc[HL], sg[4 * HL], sx[HD];

    if (tid < HL) { sh[tid] = 0.f; sc[tid] = 0.f; }
    __syncthreads();

    const float* wi = W_ih + tid * HD;
    const float* wh = W_hh + tid * HL;
    float bias = b_ih[tid] + b_hh[tid];

    for (int t = 0; t < TT; t++) {
        if (tid < HD) sx[tid] = g_pooled[(size_t)(b * TT + t) * HD + tid];
        __syncthreads();
        float acc = bias;
#pragma unroll 8
        for (int k = 0; k < HD; k++) acc += sx[k] * wi[k];
#pragma unroll 8
        for (int k = 0; k < HL; k++) acc += sh[k] * wh[k];
        sg[tid] = acc;
        __syncthreads();
        if (tid < HL) {
            float ig = sigmoidf(sg[tid]);
            float fg = sigmoidf(sg[HL + tid]);
            float gg = tanhf(sg[2 * HL + tid]);
            float og = sigmoidf(sg[3 * HL + tid]);
            float cn = fg * sc[tid] + ig * gg;
            sc[tid] = cn;
            sh[tid] = og * tanhf(cn);
        }
        __syncthreads();
    }

    if (tid < NOUT) {
        float acc = b_clf[tid];
        const float* wc = W_clf + tid * HL;
#pragma unroll 8
        for (int k = 0; k < HL; k++) acc += sh[k] * wc[k];
        out[b * NOUT + tid] = acc;
    }
}

// ---------------- launch ----------------
extern "C" void kernel_launch(void* const* d_in, const int* in_sizes, int n_in,
                              void* d_out, int out_size)
{
    const float* x      = (const float*)d_in[0];
    const int*   ei     = (const int*)  d_in[1];
    const float* W_gat  = (const float*)d_in[2];
    const float* att_s  = (const float*)d_in[3];
    const float* att_d  = (const float*)d_in[4];
    const float* b_gat  = (const float*)d_in[5];
    const float* W_ih   = (const float*)d_in[6];
    const float* W_hh   = (const float*)d_in[7];
    const float* b_ih   = (const float*)d_in[8];
    const float* b_hh   = (const float*)d_in[9];
    const float* W_clf  = (const float*)d_in[10];
    const float* b_clf  = (const float*)d_in[11];
    float* out = (float*)d_out;

    // launch order: slot 3 (ncu-profiled index) = k_gat
    k_csr_a<<<1, 1024>>>(ei);                                        // 0
    k_scatter<<<(EA + 255) / 256, 256>>>(ei);                        // 1
    k_transform<<<(G * NN) / 8, 256>>>(x, W_gat, att_s, att_d);      // 2
    k_gat<<<G * NB, 256>>>(b_gat);                                   // 3
    k_pool<<<G, 128>>>();                                            // 4
    k_lstm<<<BB, 256>>>(W_ih, W_hh, b_ih, b_hh, W_clf, b_clf, out);  // 5
}

// round 6
// speedup vs baseline: 2.5625x; 1.4275x over previous
#include <cuda_runtime.h>
#include <math.h>

#define G    128      // B*T graphs
#define NN   1000
#define FIN  16
#define HH   4
#define DD   32
#define HD   128
#define EE   16000
#define EA   17000    // + self loops
#define HL   64
#define TT   16
#define BB   8
#define NOUT 8
#define NB   125      // node-blocks per graph (NN / 8)

#define FULL 0xffffffffu

// ---- scratch (device globals; no allocations allowed) ----
__device__ __align__(128) float g_xp[G * NN * HD];   // 65.5 MB
__device__ __align__(128) float g_as[G * NN * HH];
__device__ __align__(128) float g_ad[G * NN * HH];
__device__ __align__(128) float g_part[G * NB * HD]; // per-block partial maxima
__device__ __align__(128) float g_pooled[G * HD];
__device__ __align__(128) float g_wiT[HD * 256];     // W_ih transposed [k][gate]
__device__ __align__(128) float g_whT[HL * 256];     // W_hh transposed [k][gate]
__device__ __align__(128) float g_bias[256];
__device__ int g_off[NN + 1];
__device__ int g_cursor[NN];
__device__ int g_csr[EA];

// -------- CSR stage A: histogram + scan + cursor init (one block) --------
__global__ void __launch_bounds__(1024) k_csr_a(const int* __restrict__ ei) {
    __shared__ int scnt[NN];
    __shared__ int ssum[1024];
    int t = threadIdx.x;

    if (t < NN) scnt[t] = 0;
    __syncthreads();

    for (int i = t; i < EA; i += 1024) {
        int d = (i < EE) ? ei[EE + i] : (i - EE);   // row 1 of [2,E] = dst
        atomicAdd(&scnt[d], 1);
    }
    __syncthreads();

    ssum[t] = (t < NN) ? scnt[t] : 0;
    __syncthreads();
    for (int dd = 1; dd < 1024; dd <<= 1) {
        int v = (t >= dd) ? ssum[t - dd] : 0;
        __syncthreads();
        ssum[t] += v;
        __syncthreads();
    }
    if (t < NN) {
        g_off[t + 1] = ssum[t];
        g_cursor[t]  = ssum[t] - scnt[t];           // = off[t]
    }
    if (t == 0) g_off[0] = 0;
}

// -------- CSR stage B: scatter (grid-wide) --------
__global__ void k_scatter(const int* __restrict__ ei) {
    int i = blockIdx.x * blockDim.x + threadIdx.x;
    if (i >= EA) return;
    int s, d;
    if (i < EE) { s = ei[i]; d = ei[EE + i]; }
    else        { s = d = i - EE; }                 // self loop
    int pos = atomicAdd(&g_cursor[d], 1);
    g_csr[pos] = s;
}

// -------- LSTM weight transpose (coalesced-read layout) + bias fold --------
__global__ void k_wtrans(const float* __restrict__ W_ih, const float* __restrict__ W_hh,
                         const float* __restrict__ b_ih, const float* __restrict__ b_hh)
{
    int i = blockIdx.x * 256 + threadIdx.x;         // 0 .. 256*HD-1
    int r = i & 255;                                // gate row 0..255
    int k = i >> 8;                                 // input channel
    if (k < HD) g_wiT[k * 256 + r] = W_ih[r * HD + k];
    if (k < HL) g_whT[k * 256 + r] = W_hh[r * HL + k];
    if (i < 256) g_bias[i] = b_ih[i] + b_hh[i];
}

// ---------------- node transform: xp = x @ W_gat ; a_s, a_d ----------------
__global__ void __launch_bounds__(256) k_transform(
    const float* __restrict__ x, const float* __restrict__ Wg,
    const float* __restrict__ att_s, const float* __restrict__ att_d)
{
    __shared__ float sW[FIN * HD];      // 8 KB, reused by all 8 warps
    __shared__ float sAs[HD], sAd[HD];
    int tid = threadIdx.x;
#pragma unroll
    for (int i = tid; i < FIN * HD; i += 256) sW[i] = Wg[i];
    if (tid < HD) { sAs[tid] = att_s[tid]; sAd[tid] = att_d[tid]; }
    __syncthreads();

    int w = blockIdx.x * 8 + (tid >> 5);            // warp id = (g,n)
    int lane = tid & 31;
    int g = w / NN, n = w % NN;

    float xv = 0.0f;
    if (lane < FIN) xv = x[(g * NN + n) * FIN + lane];

    float a0 = 0.f, a1 = 0.f, a2 = 0.f, a3 = 0.f;   // channels lane + 32h
#pragma unroll
    for (int f = 0; f < FIN; f++) {
        float xf = __shfl_sync(FULL, xv, f);
        const float* wr = sW + f * HD + lane;
        a0 += xf * wr[0];
        a1 += xf * wr[32];
        a2 += xf * wr[64];
        a3 += xf * wr[96];
    }
    float* xr = g_xp + (size_t)(g * NN + n) * HD + lane;
    xr[0] = a0; xr[32] = a1; xr[64] = a2; xr[96] = a3;

    float s0 = a0 * sAs[lane],      s1 = a1 * sAs[32 + lane];
    float s2 = a2 * sAs[64 + lane], s3 = a3 * sAs[96 + lane];
    float d0 = a0 * sAd[lane],      d1 = a1 * sAd[32 + lane];
    float d2 = a2 * sAd[64 + lane], d3 = a3 * sAd[96 + lane];
#pragma unroll
    for (int o = 16; o; o >>= 1) {
        s0 += __shfl_xor_sync(FULL, s0, o); s1 += __shfl_xor_sync(FULL, s1, o);
        s2 += __shfl_xor_sync(FULL, s2, o); s3 += __shfl_xor_sync(FULL, s3, o);
        d0 += __shfl_xor_sync(FULL, d0, o); d1 += __shfl_xor_sync(FULL, d1, o);
        d2 += __shfl_xor_sync(FULL, d2, o); d3 += __shfl_xor_sync(FULL, d3, o);
    }
    if (lane == 0) {
        float* ps = g_as + (size_t)(g * NN + n) * 4;
        ps[0] = s0; ps[1] = s1; ps[2] = s2; ps[3] = s3;
        float* pd = g_ad + (size_t)(g * NN + n) * 4;
        pd[0] = d0; pd[1] = d1; pd[2] = d2; pd[3] = d3;
    }
}

// -------- GAT softmax (no max-shift) + aggregate + relu + block max --------
// lane l owns channels 4l..4l+3 (head = l>>3): one LDG.128 per edge per warp
__global__ void __launch_bounds__(256) k_gat(const float* __restrict__ bg)
{
    int warp = threadIdx.x >> 5;
    int lane = threadIdx.x & 31;
    int g  = blockIdx.x / NB;
    int nb = blockIdx.x % NB;
    int n  = nb * 8 + warp;                        // dst node; 8 nodes per block

    int off0 = g_off[n];
    int cnt  = g_off[n + 1] - off0;                // >= 1 (self loop)

    const float4 adv = *(const float4*)(g_ad + (size_t)(g * NN + n) * 4);

    __shared__ int   ssrc[8][32];
    __shared__ float sexp[8][4][33];               // [head][edge], padded

    float4 acc = make_float4(0.f, 0.f, 0.f, 0.f);
    float dn0 = 0.f, dn1 = 0.f, dn2 = 0.f, dn3 = 0.f;
    const float* xpg = g_xp + (size_t)g * NN * HD;
    const float* asg = g_as + (size_t)g * NN * 4;
    int hsel = lane >> 3;

    for (int base = 0; base < cnt; base += 32) {
        int rem = cnt - base;                      // warp-uniform
        int lim = rem < 32 ? rem : 32;

        int s = 0;
        float e0 = 0.f, e1 = 0.f, e2 = 0.f, e3 = 0.f;
        if (lane < rem) {
            s = g_csr[off0 + base + lane];         // coalesced
            float4 a = *(const float4*)(asg + (size_t)s * 4);
            float v0 = a.x + adv.x; v0 = v0 >= 0.f ? v0 : 0.2f * v0;
            float v1 = a.y + adv.y; v1 = v1 >= 0.f ? v1 : 0.2f * v1;
            float v2 = a.z + adv.z; v2 = v2 >= 0.f ? v2 : 0.2f * v2;
            float v3 = a.w + adv.w; v3 = v3 >= 0.f ? v3 : 0.2f * v3;
            e0 = __expf(v0); e1 = __expf(v1); e2 = __expf(v2); e3 = __expf(v3);
            dn0 += e0; dn1 += e1; dn2 += e2; dn3 += e3;
        }
        ssrc[warp][lane] = s;
        sexp[warp][0][lane] = e0;
        sexp[warp][1][lane] = e1;
        sexp[warp][2][lane] = e2;
        sexp[warp][3][lane] = e3;
        __syncwarp();

#pragma unroll 8
        for (int q = 0; q < lim; q++) {
            int   sq = ssrc[warp][q];              // LDS broadcast
            float eh = sexp[warp][hsel][q];        // conflict-free broadcast
            float4 xr = *(const float4*)(xpg + (size_t)sq * HD + lane * 4);
            acc.x += eh * xr.x;
            acc.y += eh * xr.y;
            acc.z += eh * xr.z;
            acc.w += eh * xr.w;
        }
        __syncwarp();
    }

    // reduce denominators across the warp (once per node)
#pragma unroll
    for (int o = 16; o; o >>= 1) {
        dn0 += __shfl_xor_sync(FULL, dn0, o);
        dn1 += __shfl_xor_sync(FULL, dn1, o);
        dn2 += __shfl_xor_sync(FULL, dn2, o);
        dn3 += __shfl_xor_sync(FULL, dn3, o);
    }
    float dnh = (hsel == 0) ? dn0 : (hsel == 1) ? dn1 : (hsel == 2) ? dn2 : dn3;
    float rdn = 1.0f / dnh;

    const float4 bgv = *(const float4*)(bg + lane * 4);
    float4 o4;
    o4.x = fmaxf(acc.x * rdn + bgv.x, 0.0f);
    o4.y = fmaxf(acc.y * rdn + bgv.y, 0.0f);
    o4.z = fmaxf(acc.z * rdn + bgv.z, 0.0f);
    o4.w = fmaxf(acc.w * rdn + bgv.w, 0.0f);

    __shared__ float4 sred[8][32];
    sred[warp][lane] = o4;
    __syncthreads();

    int tid = threadIdx.x;
    if (tid < HD) {                                // channel tid
        int l = tid >> 2, c = tid & 3;
        const float* col = (const float*)&sred[0][l] + c;
        float m = col[0];
#pragma unroll
        for (int r = 1; r < 8; r++) m = fmaxf(m, col[r * 32 * 4]);
        g_part[(size_t)blockIdx.x * HD + tid] = m; // no atomics
    }
}

// ---------------- final max-pool over node-blocks ----------------
__global__ void __launch_bounds__(128) k_pool()
{
    int g = blockIdx.x, c = threadIdx.x;
    const float* p = g_part + (size_t)g * NB * HD + c;
    float m = 0.0f;                                  // relu outputs >= 0
#pragma unroll 5
    for (int b = 0; b < NB; b++) m = fmaxf(m, p[(size_t)b * HD]);
    g_pooled[(size_t)g * HD + c] = m;
}

// ---------------- LSTM (16 steps) + classifier: coalesced weights --------
__device__ __forceinline__ float sigmoidf(float x) { return 1.0f / (1.0f + __expf(-x)); }

__global__ void __launch_bounds__(256) k_lstm(
    const float* __restrict__ W_clf, const float* __restrict__ b_clf,
    float* __restrict__ out)
{
    int b = blockIdx.x;          // 8 blocks
    int tid = threadIdx.x;       // 256 = 4*HL gates
    __shared__ float sh[HL], sc[HL], sg[4 * HL], sx[HD];

    if (tid < HL) { sh[tid] = 0.f; sc[tid] = 0.f; }
    __syncthreads();

    float bias = g_bias[tid];

    for (int t = 0; t < TT; t++) {
        if (tid < HD) sx[tid] = g_pooled[(size_t)(b * TT + t) * HD + tid];
        __syncthreads();
        float acc = bias;
#pragma unroll 16
        for (int k = 0; k < HD; k++) acc += sx[k] * g_wiT[k * 256 + tid];  // coalesced
#pragma unroll 16
        for (int k = 0; k < HL; k++) acc += sh[k] * g_whT[k * 256 + tid];  // coalesced
        sg[tid] = acc;
        __syncthreads();
        if (tid < HL) {
            float ig = sigmoidf(sg[tid]);
            float fg = sigmoidf(sg[HL + tid]);
            float gg = tanhf(sg[2 * HL + tid]);
            float og = sigmoidf(sg[3 * HL + tid]);
            float cn = fg * sc[tid] + ig * gg;
            sc[tid] = cn;
            sh[tid] = og * tanhf(cn);
        }
        __syncthreads();
    }

    if (tid < NOUT) {
        float acc = b_clf[tid];
        const float* wc = W_clf + tid * HL;
#pragma unroll 8
        for (int k = 0; k < HL; k++) acc += sh[k] * wc[k];
        out[b * NOUT + tid] = acc;
    }
}

// ---------------- launch ----------------
extern "C" void kernel_launch(void* const* d_in, const int* in_sizes, int n_in,
                              void* d_out, int out_size)
{
    const float* x      = (const float*)d_in[0];
    const int*   ei     = (const int*)  d_in[1];
    const float* W_gat  = (const float*)d_in[2];
    const float* att_s  = (const float*)d_in[3];
    const float* att_d  = (const float*)d_in[4];
    const float* b_gat  = (const float*)d_in[5];
    const float* W_ih   = (const float*)d_in[6];
    const float* W_hh   = (const float*)d_in[7];
    const float* b_ih   = (const float*)d_in[8];
    const float* b_hh   = (const float*)d_in[9];
    const float* W_clf  = (const float*)d_in[10];
    const float* b_clf  = (const float*)d_in[11];
    float* out = (float*)d_out;

    // launch order: slot 3 (ncu-profiled index) = k_transform (smem version)
    k_csr_a<<<1, 1024>>>(ei);                                        // 0
    k_scatter<<<(EA + 255) / 256, 256>>>(ei);                        // 1
    k_wtrans<<<HD, 256>>>(W_ih, W_hh, b_ih, b_hh);                   // 2
    k_transform<<<(G * NN) / 8, 256>>>(x, W_gat, att_s, att_d);      // 3
    k_gat<<<G * NB, 256>>>(b_gat);                                   // 4
    k_pool<<<G, 128>>>();                                            // 5
    k_lstm<<<BB, 256>>>(W_clf, b_clf, out);                          // 6
}

// round 7
// speedup vs baseline: 4.0781x; 1.5915x over previous
#include <cuda_runtime.h>
#include <math.h>

#define G    128      // B*T graphs
#define NN   1000
#define FIN  16
#define HH   4
#define DD   32
#define HD   128
#define EE   16000
#define EA   17000    // + self loops
#define HL   64
#define TT   16
#define BB   8
#define NOUT 8
#define NB   125      // node-blocks per graph (NN / 8)

#define FULL 0xffffffffu

// ---- scratch (device globals; no allocations allowed) ----
__device__ __align__(128) float g_xp[G * NN * HD];   // 65.5 MB
__device__ __align__(128) float g_as[G * NN * HH];
__device__ __align__(128) float g_ad[G * NN * HH];
__device__ __align__(128) float g_part[G * NB * HD]; // per-block partial maxima
__device__ __align__(128) float g_pooled[G * HD];
__device__ __align__(128) float g_wiT[HD * 256];     // W_ih transposed [k][gate]
__device__ __align__(128) float g_whT[HL * 256];     // W_hh transposed [k][gate]
__device__ __align__(128) float g_bias[256];
__device__ __align__(128) float g_v[FIN * 8];        // pre-contracted att: [f][j], j=(s/d)*4+h
__device__ int g_deg[NN];
__device__ int g_off[NN + 1];
__device__ int g_cursor[NN];
__device__ int g_csr[EA];

// ---------------- CSR build (multi-kernel, measured cheap) ----------------
__global__ void k_zero() {
    int i = blockIdx.x * blockDim.x + threadIdx.x;
    if (i < NN) { g_deg[i] = 0; }
}

__global__ void k_count(const int* __restrict__ ei) {
    int i = blockIdx.x * blockDim.x + threadIdx.x;
    if (i >= EA) return;
    int d = (i < EE) ? ei[EE + i] : (i - EE);   // ei: [2,E] row-major; row1 = dst
    atomicAdd(&g_deg[d], 1);
}

__global__ void k_scan() {
    __shared__ int s[1024];
    int t = threadIdx.x;
    int c = (t < NN) ? g_deg[t] : 0;
    s[t] = c;
    __syncthreads();
    for (int d = 1; d < 1024; d <<= 1) {
        int v = (t >= d) ? s[t - d] : 0;
        __syncthreads();
        s[t] += v;
        __syncthreads();
    }
    if (t < NN) {
        g_off[t + 1] = s[t];
        g_cursor[t]  = s[t] - c;                 // = off[t]
    }
    if (t == 0) g_off[0] = 0;
}

__global__ void k_scatter(const int* __restrict__ ei) {
    int i = blockIdx.x * blockDim.x + threadIdx.x;
    if (i >= EA) return;
    int s, d;
    if (i < EE) { s = ei[i]; d = ei[EE + i]; }
    else        { s = d = i - EE; }              // self loop
    int pos = atomicAdd(&g_cursor[d], 1);
    g_csr[pos] = s;
}

// -------- LSTM weight transpose + bias fold + att pre-contraction --------
__global__ void k_wtrans(const float* __restrict__ W_ih, const float* __restrict__ W_hh,
                         const float* __restrict__ b_ih, const float* __restrict__ b_hh,
                         const float* __restrict__ Wg,
                         const float* __restrict__ att_s, const float* __restrict__ att_d)
{
    int i = blockIdx.x * 256 + threadIdx.x;      // 0 .. 256*HD-1
    int r = i & 255;                             // gate row 0..255
    int k = i >> 8;                              // input channel
    if (k < HD) g_wiT[k * 256 + r] = W_ih[r * HD + k];
    if (k < HL) g_whT[k * 256 + r] = W_hh[r * HL + k];
    if (i < 256) g_bias[i] = b_ih[i] + b_hh[i];
    // g_v[f*8+j]: j<4 -> att_src head j ; j>=4 -> att_dst head j-4
    if (i < FIN * 8) {
        int f = i >> 3, j = i & 7, h = j & 3;
        const float* av = (j < 4) ? att_s : att_d;
        float acc = 0.f;
#pragma unroll
        for (int d = 0; d < DD; d++)
            acc += Wg[f * HD + h * DD + d] * av[h * DD + d];
        g_v[i] = acc;
    }
}

// ------- node transform: xp = x @ W_gat ; a_s,a_d = x @ v  (W in regs) -------
#define TBLK 500                                  // grid blocks; 4000 warps
__global__ void __launch_bounds__(256) k_transform(
    const float* __restrict__ x, const float* __restrict__ Wg)
{
    int lane = threadIdx.x & 31;
    int gw   = blockIdx.x * 8 + (threadIdx.x >> 5); // global warp 0..3999

    // per-lane register copy of W columns (4 channels: lane+32h) and v row
    float w0[FIN], w1[FIN], w2[FIN], w3[FIN], vj[FIN];
    int j = lane & 7;
#pragma unroll
    for (int f = 0; f < FIN; f++) {
        const float* wr = Wg + f * HD + lane;
        w0[f] = wr[0];
        w1[f] = wr[32];
        w2[f] = wr[64];
        w3[f] = wr[96];
        vj[f] = g_v[f * 8 + j];
    }

    for (int w = gw; w < G * NN; w += TBLK * 8) { // w = (g,n)
        float xv = 0.0f;
        if (lane < FIN) xv = x[(size_t)w * FIN + lane];

        float a0 = 0.f, a1 = 0.f, a2 = 0.f, a3 = 0.f, av = 0.f;
#pragma unroll
        for (int f = 0; f < FIN; f++) {
            float xf = __shfl_sync(FULL, xv, f);
            a0 += xf * w0[f];
            a1 += xf * w1[f];
            a2 += xf * w2[f];
            a3 += xf * w3[f];
            av += xf * vj[f];
        }
        float* xr = g_xp + (size_t)w * HD + lane;
        xr[0] = a0; xr[32] = a1; xr[64] = a2; xr[96] = a3;
        if (lane < 4)              g_as[(size_t)w * 4 + j]       = av;
        else if (lane < 8)         g_ad[(size_t)w * 4 + (j - 4)] = av;
    }
}

// -------- GAT softmax (no max-shift) + aggregate + relu + block max --------
// lane l owns channels 4l..4l+3 (head = l>>3): one LDG.128 per edge per warp
__global__ void __launch_bounds__(256) k_gat(const float* __restrict__ bg)
{
    int warp = threadIdx.x >> 5;
    int lane = threadIdx.x & 31;
    int g  = blockIdx.x / NB;
    int nb = blockIdx.x % NB;
    int n  = nb * 8 + warp;                        // dst node; 8 nodes per block

    int off0 = g_off[n];
    int cnt  = g_off[n + 1] - off0;                // >= 1 (self loop)

    const float4 adv = *(const float4*)(g_ad + (size_t)(g * NN + n) * 4);

    __shared__ int   ssrc[8][32];
    __shared__ float sexp[8][4][33];               // [head][edge], padded

    float4 acc = make_float4(0.f, 0.f, 0.f, 0.f);
    float dn0 = 0.f, dn1 = 0.f, dn2 = 0.f, dn3 = 0.f;
    const float* xpg = g_xp + (size_t)g * NN * HD;
    const float* asg = g_as + (size_t)g * NN * 4;
    int hsel = lane >> 3;

    for (int base = 0; base < cnt; base += 32) {
        int rem = cnt - base;                      // warp-uniform
        int lim = rem < 32 ? rem : 32;

        int s = 0;
        float e0 = 0.f, e1 = 0.f, e2 = 0.f, e3 = 0.f;
        if (lane < rem) {
            s = g_csr[off0 + base + lane];         // coalesced
            float4 a = *(const float4*)(asg + (size_t)s * 4);
            float v0 = a.x + adv.x; v0 = v0 >= 0.f ? v0 : 0.2f * v0;
            float v1 = a.y + adv.y; v1 = v1 >= 0.f ? v1 : 0.2f * v1;
            float v2 = a.z + adv.z; v2 = v2 >= 0.f ? v2 : 0.2f * v2;
            float v3 = a.w + adv.w; v3 = v3 >= 0.f ? v3 : 0.2f * v3;
            e0 = __expf(v0); e1 = __expf(v1); e2 = __expf(v2); e3 = __expf(v3);
            dn0 += e0; dn1 += e1; dn2 += e2; dn3 += e3;
        }
        ssrc[warp][lane] = s;
        sexp[warp][0][lane] = e0;
        sexp[warp][1][lane] = e1;
        sexp[warp][2][lane] = e2;
        sexp[warp][3][lane] = e3;
        __syncwarp();

#pragma unroll 8
        for (int q = 0; q < lim; q++) {
            int   sq = ssrc[warp][q];              // LDS broadcast
            float eh = sexp[warp][hsel][q];        // conflict-free broadcast
            float4 xr = *(const float4*)(xpg + (size_t)sq * HD + lane * 4);
            acc.x += eh * xr.x;
            acc.y += eh * xr.y;
            acc.z += eh * xr.z;
            acc.w += eh * xr.w;
        }
        __syncwarp();
    }

    // reduce denominators across the warp (once per node)
#pragma unroll
    for (int o = 16; o; o >>= 1) {
        dn0 += __shfl_xor_sync(FULL, dn0, o);
        dn1 += __shfl_xor_sync(FULL, dn1, o);
        dn2 += __shfl_xor_sync(FULL, dn2, o);
        dn3 += __shfl_xor_sync(FULL, dn3, o);
    }
    float dnh = (hsel == 0) ? dn0 : (hsel == 1) ? dn1 : (hsel == 2) ? dn2 : dn3;
    float rdn = 1.0f / dnh;

    const float4 bgv = *(const float4*)(bg + lane * 4);
    float4 o4;
    o4.x = fmaxf(acc.x * rdn + bgv.x, 0.0f);
    o4.y = fmaxf(acc.y * rdn + bgv.y, 0.0f);
    o4.z = fmaxf(acc.z * rdn + bgv.z, 0.0f);
    o4.w = fmaxf(acc.w * rdn + bgv.w, 0.0f);

    __shared__ float4 sred[8][32];
    sred[warp][lane] = o4;
    __syncthreads();

    int tid = threadIdx.x;
    if (tid < HD) {                                // channel tid
        int l = tid >> 2, c = tid & 3;
        const float* col = (const float*)&sred[0][l] + c;
        float m = col[0];
#pragma unroll
        for (int r = 1; r < 8; r++) m = fmaxf(m, col[r * 32 * 4]);
        g_part[(size_t)blockIdx.x * HD + tid] = m; // no atomics
    }
}

// ---------------- final max-pool over node-blocks ----------------
__global__ void __launch_bounds__(128) k_pool()
{
    int g = blockIdx.x, c = threadIdx.x;
    const float* p = g_part + (size_t)g * NB * HD + c;
    float m = 0.0f;                                  // relu outputs >= 0
#pragma unroll 5
    for (int b = 0; b < NB; b++) m = fmaxf(m, p[(size_t)b * HD]);
    g_pooled[(size_t)g * HD + c] = m;
}

// ---------------- LSTM (16 steps) + classifier: coalesced weights --------
__device__ __forceinline__ float sigmoidf(float x) { return 1.0f / (1.0f + __expf(-x)); }

__global__ void __launch_bounds__(256) k_lstm(
    const float* __restrict__ W_clf, const float* __restrict__ b_clf,
    float* __restrict__ out)
{
    int b = blockIdx.x;          // 8 blocks
    int tid = threadIdx.x;       // 256 = 4*HL gates
    __shared__ float sh[HL], sc[HL], sg[4 * HL], sx[HD];

    if (tid < HL) { sh[tid] = 0.f; sc[tid] = 0.f; }
    __syncthreads();

    float bias = g_bias[tid];

    for (int t = 0; t < TT; t++) {
        if (tid < HD) sx[tid] = g_pooled[(size_t)(b * TT + t) * HD + tid];
        __syncthreads();
        float acc = bias;
#pragma unroll 16
        for (int k = 0; k < HD; k++) acc += sx[k] * g_wiT[k * 256 + tid];  // coalesced
#pragma unroll 16
        for (int k = 0; k < HL; k++) acc += sh[k] * g_whT[k * 256 + tid];  // coalesced
        sg[tid] = acc;
        __syncthreads();
        if (tid < HL) {
            float ig = sigmoidf(sg[tid]);
            float fg = sigmoidf(sg[HL + tid]);
            float gg = tanhf(sg[2 * HL + tid]);
            float og = sigmoidf(sg[3 * HL + tid]);
            float cn = fg * sc[tid] + ig * gg;
            sc[tid] = cn;
            sh[tid] = og * tanhf(cn);
        }
        __syncthreads();
    }

    if (tid < NOUT) {
        float acc = b_clf[tid];
        const float* wc = W_clf + tid * HL;
#pragma unroll 8
        for (int k = 0; k < HL; k++) acc += sh[k] * wc[k];
        out[b * NOUT + tid] = acc;
    }
}

// ---------------- launch ----------------
extern "C" void kernel_launch(void* const* d_in, const int* in_sizes, int n_in,
                              void* d_out, int out_size)
{
    const float* x      = (const float*)d_in[0];
    const int*   ei     = (const int*)  d_in[1];
    const float* W_gat  = (const float*)d_in[2];
    const float* att_s  = (const float*)d_in[3];
    const float* att_d  = (const float*)d_in[4];
    const float* b_gat  = (const float*)d_in[5];
    const float* W_ih   = (const float*)d_in[6];
    const float* W_hh   = (const float*)d_in[7];
    const float* b_ih   = (const float*)d_in[8];
    const float* b_hh   = (const float*)d_in[9];
    const float* W_clf  = (const float*)d_in[10];
    const float* b_clf  = (const float*)d_in[11];
    float* out = (float*)d_out;

    // slot 3 (ncu-profiled index) = new k_transform
    k_zero<<<(NN + 255) / 256, 256>>>();                                     // 0
    k_count<<<(EA + 255) / 256, 256>>>(ei);                                  // 1
    k_wtrans<<<HD, 256>>>(W_ih, W_hh, b_ih, b_hh, W_gat, att_s, att_d);      // 2
    k_transform<<<TBLK, 256>>>(x, W_gat);                                    // 3
    k_scan<<<1, 1024>>>();                                                   // 4
    k_scatter<<<(EA + 255) / 256, 256>>>(ei);                                // 5
    k_gat<<<G * NB, 256>>>(b_gat);                                           // 6
    k_pool<<<G, 128>>>();                                                    // 7
    k_lstm<<<BB, 256>>>(W_clf, b_clf, out);                                  // 8
}

// round 8
// speedup vs baseline: 4.8852x; 1.1979x over previous
#include <cuda_runtime.h>
#include <cuda_fp16.h>
#include <math.h>

#define G    128      // B*T graphs
#define NN   1000
#define FIN  16
#define HH   4
#define DD   32
#define HD   128
#define EE   16000
#define EA   17000    // + self loops
#define HL   64
#define TT   16
#define BB   8
#define NOUT 8
#define NB   125      // node-blocks per graph (NN / 8)

#define FULL 0xffffffffu

// ---- scratch (device globals; no allocations allowed) ----
__device__ __align__(128) __half g_xph[G * NN * HD]; // 32.8 MB, fp16 features
__device__ __align__(128) float g_as[G * NN * HH];
__device__ __align__(128) float g_ad[G * NN * HH];
__device__ __align__(128) float g_part[G * NB * HD]; // per-block partial maxima
__device__ __align__(128) float g_pooled[G * HD];
__device__ __align__(128) float g_wiT[HD * 256];     // W_ih transposed [k][gate]
__device__ __align__(128) float g_whT[HL * 256];     // W_hh transposed [k][gate]
__device__ __align__(128) float g_bias[256];
__device__ int g_deg[NN];                            // zero-init; k_scan re-zeroes
__device__ int g_off[NN + 1];
__device__ int g_cursor[NN];
__device__ int g_csr[EA];

// ------- transform: xp(fp16) = x @ W_gat ; a_s,a_d = x @ v ; + edge count ----
#define TBLK 500                                  // 4000 warps; 128000 threads
__global__ void __launch_bounds__(256) k_transform(
    const float* __restrict__ x, const float* __restrict__ Wg,
    const float* __restrict__ att_s, const float* __restrict__ att_d,
    const int* __restrict__ ei)
{
    __shared__ float sv[FIN][8];                  // pre-contracted att
    int tid = threadIdx.x;

    // fused edge-degree count (g_deg zeroed by previous run's k_scan)
    int eidx = blockIdx.x * 256 + tid;
    if (eidx < EA) {
        int d = (eidx < EE) ? ei[EE + eidx] : (eidx - EE);   // row1 = dst
        atomicAdd(&g_deg[d], 1);
    }

    // sv[f][j]: j<4 -> att_src head j ; j>=4 -> att_dst head j-4
    if (tid < FIN * 8) {
        int f = tid >> 3, j = tid & 7, h = j & 3;
        const float* av = (j < 4) ? att_s : att_d;
        float acc = 0.f;
#pragma unroll
        for (int d = 0; d < DD; d++)
            acc += Wg[f * HD + h * DD + d] * av[h * DD + d];
        sv[f][j] = acc;
    }

    int lane = tid & 31;
    float4 wf[FIN];                               // W cols 4l..4l+3 in regs
#pragma unroll
    for (int f = 0; f < FIN; f++)
        wf[f] = *(const float4*)(Wg + f * HD + 4 * lane);
    __syncthreads();

    int j = lane & 7;
    float vj[FIN];
#pragma unroll
    for (int f = 0; f < FIN; f++) vj[f] = sv[f][j];

    int gw = blockIdx.x * 8 + (tid >> 5);         // global warp 0..3999
    for (int w = gw; w < G * NN; w += TBLK * 8) { // w = (g,n); 32 iters, uniform
        float xv = 0.0f;
        if (lane < FIN) xv = x[(size_t)w * FIN + lane];

        float a0 = 0.f, a1 = 0.f, a2 = 0.f, a3 = 0.f, av = 0.f;
#pragma unroll
        for (int f = 0; f < FIN; f++) {
            float xf = __shfl_sync(FULL, xv, f);
            a0 += xf * wf[f].x;
            a1 += xf * wf[f].y;
            a2 += xf * wf[f].z;
            a3 += xf * wf[f].w;
            av += xf * vj[f];
        }
        union { __half2 h[2]; uint2 u; } pk;
        pk.h[0] = __floats2half2_rn(a0, a1);
        pk.h[1] = __floats2half2_rn(a2, a3);
        *(uint2*)(g_xph + (size_t)w * HD + 4 * lane) = pk.u;   // 8B, coalesced

        if (lane < 4)      g_as[(size_t)w * 4 + j]       = av;
        else if (lane < 8) g_ad[(size_t)w * 4 + (j - 4)] = av;
    }
}

// -------- CSR scan (single block) — also resets g_deg for graph replay -----
__global__ void k_scan() {
    __shared__ int s[1024];
    int t = threadIdx.x;
    int c = (t < NN) ? g_deg[t] : 0;
    if (t < NN) g_deg[t] = 0;                      // ready for next replay
    s[t] = c;
    __syncthreads();
    for (int d = 1; d < 1024; d <<= 1) {
        int v = (t >= d) ? s[t - d] : 0;
        __syncthreads();
        s[t] += v;
        __syncthreads();
    }
    if (t < NN) {
        g_off[t + 1] = s[t];
        g_cursor[t]  = s[t] - c;                   // = off[t]
    }
    if (t == 0) g_off[0] = 0;
}

__global__ void k_scatter(const int* __restrict__ ei) {
    int i = blockIdx.x * blockDim.x + threadIdx.x;
    if (i >= EA) return;
    int s, d;
    if (i < EE) { s = ei[i]; d = ei[EE + i]; }
    else        { s = d = i - EE; }                // self loop
    int pos = atomicAdd(&g_cursor[d], 1);
    g_csr[pos] = s;
}

// -------- GAT softmax (no max-shift) + aggregate + relu + block max --------
// lane l owns channels 4l..4l+3 (head = l>>3); fp16 gather = 8B/lane/edge
__global__ void __launch_bounds__(256, 6) k_gat(const float* __restrict__ bg)
{
    int warp = threadIdx.x >> 5;
    int lane = threadIdx.x & 31;
    int g  = blockIdx.x / NB;
    int nb = blockIdx.x % NB;
    int n  = nb * 8 + warp;                        // dst node; 8 nodes per block

    int off0 = g_off[n];
    int cnt  = g_off[n + 1] - off0;                // >= 1 (self loop)

    const float4 adv = *(const float4*)(g_ad + (size_t)(g * NN + n) * 4);

    __shared__ int   ssrc[8][32];
    __shared__ float sexp[8][4][33];               // [head][edge], padded

    float4 acc = make_float4(0.f, 0.f, 0.f, 0.f);
    float dn0 = 0.f, dn1 = 0.f, dn2 = 0.f, dn3 = 0.f;
    const __half* xpg = g_xph + (size_t)g * NN * HD;
    const float*  asg = g_as  + (size_t)g * NN * 4;
    int hsel = lane >> 3;

    for (int base = 0; base < cnt; base += 32) {
        int rem = cnt - base;                      // warp-uniform
        int lim = rem < 32 ? rem : 32;

        int s = 0;
        float e0 = 0.f, e1 = 0.f, e2 = 0.f, e3 = 0.f;
        if (lane < rem) {
            s = g_csr[off0 + base + lane];         // coalesced
            float4 a = *(const float4*)(asg + (size_t)s * 4);
            float v0 = a.x + adv.x; v0 = v0 >= 0.f ? v0 : 0.2f * v0;
            float v1 = a.y + adv.y; v1 = v1 >= 0.f ? v1 : 0.2f * v1;
            float v2 = a.z + adv.z; v2 = v2 >= 0.f ? v2 : 0.2f * v2;
            float v3 = a.w + adv.w; v3 = v3 >= 0.f ? v3 : 0.2f * v3;
            e0 = __expf(v0); e1 = __expf(v1); e2 = __expf(v2); e3 = __expf(v3);
            dn0 += e0; dn1 += e1; dn2 += e2; dn3 += e3;
        }
        ssrc[warp][lane] = s;
        sexp[warp][0][lane] = e0;
        sexp[warp][1][lane] = e1;
        sexp[warp][2][lane] = e2;
        sexp[warp][3][lane] = e3;
        __syncwarp();

#pragma unroll 8
        for (int q = 0; q < lim; q++) {
            int   sq = ssrc[warp][q];              // LDS broadcast
            float eh = sexp[warp][hsel][q];        // conflict-free broadcast
            union { uint2 u; __half2 h[2]; } pk;
            pk.u = *(const uint2*)(xpg + (size_t)sq * HD + 4 * lane);
            float2 f01 = __half22float2(pk.h[0]);
            float2 f23 = __half22float2(pk.h[1]);
            acc.x += eh * f01.x;
            acc.y += eh * f01.y;
            acc.z += eh * f23.x;
            acc.w += eh * f23.y;
        }
        __syncwarp();
    }

    // reduce denominators across the warp (once per node)
#pragma unroll
    for (int o = 16; o; o >>= 1) {
        dn0 += __shfl_xor_sync(FULL, dn0, o);
        dn1 += __shfl_xor_sync(FULL, dn1, o);
        dn2 += __shfl_xor_sync(FULL, dn2, o);
        dn3 += __shfl_xor_sync(FULL, dn3, o);
    }
    float dnh = (hsel == 0) ? dn0 : (hsel == 1) ? dn1 : (hsel == 2) ? dn2 : dn3;
    float rdn = 1.0f / dnh;

    const float4 bgv = *(const float4*)(bg + lane * 4);
    float4 o4;
    o4.x = fmaxf(acc.x * rdn + bgv.x, 0.0f);
    o4.y = fmaxf(acc.y * rdn + bgv.y, 0.0f);
    o4.z = fmaxf(acc.z * rdn + bgv.z, 0.0f);
    o4.w = fmaxf(acc.w * rdn + bgv.w, 0.0f);

    __shared__ float4 sred[8][32];
    sred[warp][lane] = o4;
    __syncthreads();

    int tid = threadIdx.x;
    if (tid < HD) {                                // channel tid = 4l+c
        int l = tid >> 2, c = tid & 3;
        const float* col = (const float*)&sred[0][l] + c;
        float m = col[0];
#pragma unroll
        for (int r = 1; r < 8; r++) m = fmaxf(m, col[r * 32 * 4]);
        g_part[(size_t)blockIdx.x * HD + tid] = m; // no atomics
    }
}

// ---------------- final max-pool over node-blocks ----------------
__global__ void __launch_bounds__(128) k_pool()
{
    int g = blockIdx.x, c = threadIdx.x;
    const float* p = g_part + (size_t)g * NB * HD + c;
    float m = 0.0f;                                  // relu outputs >= 0
#pragma unroll 5
    for (int b = 0; b < NB; b++) m = fmaxf(m, p[(size_t)b * HD]);
    g_pooled[(size_t)g * HD + c] = m;
}

// -------- LSTM weight transpose (coalesced-read layout) + bias fold --------
__global__ void k_wtrans(const float* __restrict__ W_ih, const float* __restrict__ W_hh,
                         const float* __restrict__ b_ih, const float* __restrict__ b_hh)
{
    int i = blockIdx.x * 256 + threadIdx.x;         // 0 .. 256*HD-1
    int r = i & 255;                                // gate row 0..255
    int k = i >> 8;                                 // input channel
    if (k < HD) g_wiT[k * 256 + r] = W_ih[r * HD + k];
    if (k < HL) g_whT[k * 256 + r] = W_hh[r * HL + k];
    if (i < 256) g_bias[i] = b_ih[i] + b_hh[i];
}

// ---------------- LSTM (16 steps) + classifier: coalesced weights --------
__device__ __forceinline__ float sigmoidf(float x) { return 1.0f / (1.0f + __expf(-x)); }

__global__ void __launch_bounds__(256) k_lstm(
    const float* __restrict__ W_clf, const float* __restrict__ b_clf,
    float* __restrict__ out)
{
    int b = blockIdx.x;          // 8 blocks
    int tid = threadIdx.x;       // 256 = 4*HL gates
    __shared__ float sh[HL], sc[HL], sg[4 * HL], sx[HD];

    if (tid < HL) { sh[tid] = 0.f; sc[tid] = 0.f; }
    __syncthreads();

    float bias = g_bias[tid];

    for (int t = 0; t < TT; t++) {
        if (tid < HD) sx[tid] = g_pooled[(size_t)(b * TT + t) * HD + tid];
        __syncthreads();
        float acc = bias;
#pragma unroll 16
        for (int k = 0; k < HD; k++) acc += sx[k] * g_wiT[k * 256 + tid];  // coalesced
#pragma unroll 16
        for (int k = 0; k < HL; k++) acc += sh[k] * g_whT[k * 256 + tid];  // coalesced
        sg[tid] = acc;
        __syncthreads();
        if (tid < HL) {
            float ig = sigmoidf(sg[tid]);
            float fg = sigmoidf(sg[HL + tid]);
            float gg = tanhf(sg[2 * HL + tid]);
            float og = sigmoidf(sg[3 * HL + tid]);
            float cn = fg * sc[tid] + ig * gg;
            sc[tid] = cn;
            sh[tid] = og * tanhf(cn);
        }
        __syncthreads();
    }

    if (tid < NOUT) {
        float acc = b_clf[tid];
        const float* wc = W_clf + tid * HL;
#pragma unroll 8
        for (int k = 0; k < HL; k++) acc += sh[k] * wc[k];
        out[b * NOUT + tid] = acc;
    }
}

// ---------------- launch ----------------
extern "C" void kernel_launch(void* const* d_in, const int* in_sizes, int n_in,
                              void* d_out, int out_size)
{
    const float* x      = (const float*)d_in[0];
    const int*   ei     = (const int*)  d_in[1];
    const float* W_gat  = (const float*)d_in[2];
    const float* att_s  = (const float*)d_in[3];
    const float* att_d  = (const float*)d_in[4];
    const float* b_gat  = (const float*)d_in[5];
    const float* W_ih   = (const float*)d_in[6];
    const float* W_hh   = (const float*)d_in[7];
    const float* b_ih   = (const float*)d_in[8];
    const float* b_hh   = (const float*)d_in[9];
    const float* W_clf  = (const float*)d_in[10];
    const float* b_clf  = (const float*)d_in[11];
    float* out = (float*)d_out;

    // slot 3 (ncu-profiled index) = k_gat
    k_transform<<<TBLK, 256>>>(x, W_gat, att_s, att_d, ei);          // 0 (+count,+g_v)
    k_scan<<<1, 1024>>>();                                           // 1 (resets g_deg)
    k_scatter<<<(EA + 255) / 256, 256>>>(ei);                        // 2
    k_gat<<<G * NB, 256>>>(b_gat);                                   // 3  <- profiled
    k_pool<<<G, 128>>>();                                            // 4
    k_wtrans<<<HD, 256>>>(W_ih, W_hh, b_ih, b_hh);                   // 5
    k_lstm<<<BB, 256>>>(W_clf, b_clf, out);                          // 6
}

// round 9
// speedup vs baseline: 5.2742x; 1.0796x over previous
#include <cuda_runtime.h>
#include <cuda_fp16.h>
#include <math.h>

#define G    128      // B*T graphs
#define NN   1000
#define FIN  16
#define HH   4
#define DD   32
#define HD   128
#define EE   16000
#define EA   17000    // + self loops
#define HL   64
#define TT   16
#define BB   8
#define NOUT 8
#define NB   125      // node-blocks per graph (NN / 8)

#define FULL 0xffffffffu

// ---- scratch (device globals; no allocations allowed) ----
__device__ __align__(128) __half g_xph[G * NN * HD]; // 32.8 MB, fp16 features
__device__ __align__(128) float g_as[G * NN * HH];
__device__ __align__(128) float g_ad[G * NN * HH];
__device__ __align__(128) float g_part[G * NB * HD]; // per-block partial maxima
__device__ __align__(128) float g_pooled[G * HD];
__device__ __align__(128) float g_wiT[HD * 256];     // W_ih transposed [k][gate]
__device__ __align__(128) float g_whT[HL * 256];     // W_hh transposed [k][gate]
__device__ __align__(128) float g_bias[256];
__device__ int g_deg[NN];                            // zero-init; k_scan re-zeroes
__device__ int g_off[NN + 1];
__device__ int g_cursor[NN];
__device__ int g_csr[EA];

// ------- transform: xp(fp16) = x @ W_gat ; a_s,a_d = x @ v ; + edge count ----
#define TBLK 444                                  // ~3 blocks/SM, one wave
__global__ void __launch_bounds__(256, 3) k_transform(
    const float* __restrict__ x, const float* __restrict__ Wg,
    const float* __restrict__ att_s, const float* __restrict__ att_d,
    const int* __restrict__ ei)
{
    __shared__ float sv[FIN][8];                  // pre-contracted att
    int tid = threadIdx.x;

    // fused edge-degree count (g_deg zeroed by previous run's k_scan)
    int eidx = blockIdx.x * 256 + tid;
    if (eidx < EA) {
        int d = (eidx < EE) ? ei[EE + eidx] : (eidx - EE);   // row1 = dst
        atomicAdd(&g_deg[d], 1);
    }

    // sv[f][j]: j<4 -> att_src head j ; j>=4 -> att_dst head j-4
    if (tid < FIN * 8) {
        int f = tid >> 3, j = tid & 7, h = j & 3;
        const float* av = (j < 4) ? att_s : att_d;
        float acc = 0.f;
#pragma unroll
        for (int d = 0; d < DD; d++)
            acc += Wg[f * HD + h * DD + d] * av[h * DD + d];
        sv[f][j] = acc;
    }

    int lane = tid & 31;
    float4 wf[FIN];                               // W cols 4l..4l+3 in regs
#pragma unroll
    for (int f = 0; f < FIN; f++)
        wf[f] = *(const float4*)(Wg + f * HD + 4 * lane);
    __syncthreads();

    int j = lane & 7;
    int gw = blockIdx.x * 8 + (tid >> 5);         // global warp
    for (int w = gw; w < G * NN; w += TBLK * 8) { // w = (g,n)
        float xv = 0.0f;
        if (lane < FIN) xv = x[(size_t)w * FIN + lane];

        float a0 = 0.f, a1 = 0.f, a2 = 0.f, a3 = 0.f, av = 0.f;
#pragma unroll
        for (int f = 0; f < FIN; f++) {
            float xf = __shfl_sync(FULL, xv, f);
            a0 += xf * wf[f].x;
            a1 += xf * wf[f].y;
            a2 += xf * wf[f].z;
            a3 += xf * wf[f].w;
            av += xf * sv[f][j];                  // LDS, conflict-free
        }
        union { __half2 h[2]; uint2 u; } pk;
        pk.h[0] = __floats2half2_rn(a0, a1);
        pk.h[1] = __floats2half2_rn(a2, a3);
        *(uint2*)(g_xph + (size_t)w * HD + 4 * lane) = pk.u;   // 8B, coalesced

        if (lane < 4)      g_as[(size_t)w * 4 + j]       = av;
        else if (lane < 8) g_ad[(size_t)w * 4 + (j - 4)] = av;
    }
}

// -------- CSR scan (single block) — also resets g_deg for graph replay -----
__global__ void k_scan() {
    __shared__ int s[1024];
    int t = threadIdx.x;
    int c = (t < NN) ? g_deg[t] : 0;
    if (t < NN) g_deg[t] = 0;                      // ready for next replay
    s[t] = c;
    __syncthreads();
    for (int d = 1; d < 1024; d <<= 1) {
        int v = (t >= d) ? s[t - d] : 0;
        __syncthreads();
        s[t] += v;
        __syncthreads();
    }
    if (t < NN) {
        g_off[t + 1] = s[t];
        g_cursor[t]  = s[t] - c;                   // = off[t]
    }
    if (t == 0) g_off[0] = 0;
}

__global__ void k_scatter(const int* __restrict__ ei) {
    int i = blockIdx.x * blockDim.x + threadIdx.x;
    if (i >= EA) return;
    int s, d;
    if (i < EE) { s = ei[i]; d = ei[EE + i]; }
    else        { s = d = i - EE; }                // self loop
    int pos = atomicAdd(&g_cursor[d], 1);
    g_csr[pos] = s;
}

// -------- GAT softmax (no max-shift) + aggregate + relu + block max --------
// lane l owns channels 4l..4l+3 (head = l>>3); fp16 gather = 8B/lane/edge
__global__ void __launch_bounds__(256, 6) k_gat(const float* __restrict__ bg)
{
    int warp = threadIdx.x >> 5;
    int lane = threadIdx.x & 31;
    int g  = blockIdx.x / NB;
    int nb = blockIdx.x % NB;
    int n  = nb * 8 + warp;                        // dst node; 8 nodes per block

    int off0 = g_off[n];
    int cnt  = g_off[n + 1] - off0;                // >= 1 (self loop)

    const float4 adv = *(const float4*)(g_ad + (size_t)(g * NN + n) * 4);

    __shared__ int   soff[8][32];                  // pre-scaled row offsets
    __shared__ float sexp[8][4][33];               // [head][edge], padded

    float4 acc = make_float4(0.f, 0.f, 0.f, 0.f);
    float dn0 = 0.f, dn1 = 0.f, dn2 = 0.f, dn3 = 0.f;
    const __half* xpg = g_xph + (size_t)g * NN * HD + 4 * lane;
    const float*  asg = g_as  + (size_t)g * NN * 4;
    int hsel = lane >> 3;

    for (int base = 0; base < cnt; base += 32) {
        int rem = cnt - base;                      // warp-uniform
        int lim = rem < 32 ? rem : 32;

        int s = 0;
        float e0 = 0.f, e1 = 0.f, e2 = 0.f, e3 = 0.f;
        if (lane < rem) {
            s = g_csr[off0 + base + lane];         // coalesced
            float4 a = *(const float4*)(asg + (size_t)s * 4);
            float v0 = a.x + adv.x; v0 = v0 >= 0.f ? v0 : 0.2f * v0;
            float v1 = a.y + adv.y; v1 = v1 >= 0.f ? v1 : 0.2f * v1;
            float v2 = a.z + adv.z; v2 = v2 >= 0.f ? v2 : 0.2f * v2;
            float v3 = a.w + adv.w; v3 = v3 >= 0.f ? v3 : 0.2f * v3;
            e0 = __expf(v0); e1 = __expf(v1); e2 = __expf(v2); e3 = __expf(v3);
            dn0 += e0; dn1 += e1; dn2 += e2; dn3 += e3;
        }
        soff[warp][lane] = s * HD;                 // element offset of src row
        sexp[warp][0][lane] = e0;
        sexp[warp][1][lane] = e1;
        sexp[warp][2][lane] = e2;
        sexp[warp][3][lane] = e3;
        __syncwarp();

#pragma unroll 8
        for (int q = 0; q < lim; q++) {
            int   oq = soff[warp][q];              // LDS broadcast
            float eh = sexp[warp][hsel][q];        // conflict-free broadcast
            union { uint2 u; __half2 h[2]; } pk;
            pk.u = *(const uint2*)(xpg + oq);
            float2 f01 = __half22float2(pk.h[0]);
            float2 f23 = __half22float2(pk.h[1]);
            acc.x += eh * f01.x;
            acc.y += eh * f01.y;
            acc.z += eh * f23.x;
            acc.w += eh * f23.y;
        }
        __syncwarp();
    }

    // reduce denominators across the warp (once per node)
#pragma unroll
    for (int o = 16; o; o >>= 1) {
        dn0 += __shfl_xor_sync(FULL, dn0, o);
        dn1 += __shfl_xor_sync(FULL, dn1, o);
        dn2 += __shfl_xor_sync(FULL, dn2, o);
        dn3 += __shfl_xor_sync(FULL, dn3, o);
    }
    float dnh = (hsel == 0) ? dn0 : (hsel == 1) ? dn1 : (hsel == 2) ? dn2 : dn3;
    float rdn = 1.0f / dnh;

    const float4 bgv = *(const float4*)(bg + lane * 4);
    float4 o4;
    o4.x = fmaxf(acc.x * rdn + bgv.x, 0.0f);
    o4.y = fmaxf(acc.y * rdn + bgv.y, 0.0f);
    o4.z = fmaxf(acc.z * rdn + bgv.z, 0.0f);
    o4.w = fmaxf(acc.w * rdn + bgv.w, 0.0f);

    __shared__ float4 sred[8][32];
    sred[warp][lane] = o4;
    __syncthreads();

    int tid = threadIdx.x;
    if (tid < HD) {                                // channel tid = 4l+c
        int l = tid >> 2, c = tid & 3;
        const float* col = (const float*)&sred[0][l] + c;
        float m = col[0];
#pragma unroll
        for (int r = 1; r < 8; r++) m = fmaxf(m, col[r * 32 * 4]);
        g_part[(size_t)blockIdx.x * HD + tid] = m; // no atomics
    }
}

// ------ fused: final max-pool (blocks < G) + LSTM weight transpose ------
__global__ void __launch_bounds__(128) k_poolw(
    const float* __restrict__ W_ih, const float* __restrict__ W_hh,
    const float* __restrict__ b_ih, const float* __restrict__ b_hh)
{
    int tid = threadIdx.x;
    if (blockIdx.x < G) {
        int g = blockIdx.x;
        int warp = tid >> 5, lane = tid & 31;
        const float* p = g_part + (size_t)g * NB * HD + 4 * lane;
        float4 m = make_float4(0.f, 0.f, 0.f, 0.f);
        for (int b = warp; b < NB; b += 4) {       // warp reads whole 512B row
            float4 v = *(const float4*)(p + (size_t)b * HD);
            m.x = fmaxf(m.x, v.x); m.y = fmaxf(m.y, v.y);
            m.z = fmaxf(m.z, v.z); m.w = fmaxf(m.w, v.w);
        }
        __shared__ float4 sm[4][32];
        sm[warp][lane] = m;
        __syncthreads();
        if (warp == 0) {
            float4 a = sm[0][lane];
#pragma unroll
            for (int r = 1; r < 4; r++) {
                float4 v = sm[r][lane];
                a.x = fmaxf(a.x, v.x); a.y = fmaxf(a.y, v.y);
                a.z = fmaxf(a.z, v.z); a.w = fmaxf(a.w, v.w);
            }
            *(float4*)(g_pooled + (size_t)g * HD + 4 * lane) = a;
        }
    } else {
        int i = (blockIdx.x - G) * 128 + tid;      // 0 .. 32767
        int r = i & 255;                           // gate row
        int k = i >> 8;                            // input channel
        if (k < HD) g_wiT[k * 256 + r] = W_ih[r * HD + k];
        if (k < HL) g_whT[k * 256 + r] = W_hh[r * HL + k];
        if (i < 256) g_bias[i] = b_ih[i] + b_hh[i];
    }
}

// ---------------- LSTM (16 steps) + classifier: coalesced weights --------
__device__ __forceinline__ float sigmoidf(float x) { return 1.0f / (1.0f + __expf(-x)); }

__global__ void __launch_bounds__(256) k_lstm(
    const float* __restrict__ W_clf, const float* __restrict__ b_clf,
    float* __restrict__ out)
{
    int b = blockIdx.x;          // 8 blocks
    int tid = threadIdx.x;       // 256 = 4*HL gates
    __shared__ float sh[HL], sc[HL], sg[4 * HL], sx[HD];

    if (tid < HL) { sh[tid] = 0.f; sc[tid] = 0.f; }
    __syncthreads();

    float bias = g_bias[tid];

    for (int t = 0; t < TT; t++) {
        if (tid < HD) sx[tid] = g_pooled[(size_t)(b * TT + t) * HD + tid];
        __syncthreads();
        float acc = bias;
#pragma unroll 16
        for (int k = 0; k < HD; k++) acc += sx[k] * g_wiT[k * 256 + tid];  // coalesced
#pragma unroll 16
        for (int k = 0; k < HL; k++) acc += sh[k] * g_whT[k * 256 + tid];  // coalesced
        sg[tid] = acc;
        __syncthreads();
        if (tid < HL) {
            float ig = sigmoidf(sg[tid]);
            float fg = sigmoidf(sg[HL + tid]);
            float gg = tanhf(sg[2 * HL + tid]);
            float og = sigmoidf(sg[3 * HL + tid]);
            float cn = fg * sc[tid] + ig * gg;
            sc[tid] = cn;
            sh[tid] = og * tanhf(cn);
        }
        __syncthreads();
    }

    if (tid < NOUT) {
        float acc = b_clf[tid];
        const float* wc = W_clf + tid * HL;
#pragma unroll 8
        for (int k = 0; k < HL; k++) acc += sh[k] * wc[k];
        out[b * NOUT + tid] = acc;
    }
}

// ---------------- launch ----------------
extern "C" void kernel_launch(void* const* d_in, const int* in_sizes, int n_in,
                              void* d_out, int out_size)
{
    const float* x      = (const float*)d_in[0];
    const int*   ei     = (const int*)  d_in[1];
    const float* W_gat  = (const float*)d_in[2];
    const float* att_s  = (const float*)d_in[3];
    const float* att_d  = (const float*)d_in[4];
    const float* b_gat  = (const float*)d_in[5];
    const float* W_ih   = (const float*)d_in[6];
    const float* W_hh   = (const float*)d_in[7];
    const float* b_ih   = (const float*)d_in[8];
    const float* b_hh   = (const float*)d_in[9];
    const float* W_clf  = (const float*)d_in[10];
    const float* b_clf  = (const float*)d_in[11];
    float* out = (float*)d_out;

    // slot 3 (ncu-profiled index) = k_gat
    k_transform<<<TBLK, 256>>>(x, W_gat, att_s, att_d, ei);          // 0 (+count)
    k_scan<<<1, 1024>>>();                                           // 1 (resets g_deg)
    k_scatter<<<(EA + 255) / 256, 256>>>(ei);                        // 2
    k_gat<<<G * NB, 256>>>(b_gat);                                   // 3  <- profiled
    k_poolw<<<G + 256, 128>>>(W_ih, W_hh, b_ih, b_hh);               // 4
    k_lstm<<<BB, 256>>>(W_clf, b_clf, out);                          // 5
}